// round 1
// baseline (speedup 1.0000x reference)
#include <cuda_runtime.h>
#include <math.h>

#define HID   512
#define BATCH 64
#define NSEQ  128
#define TENC  256
#define TDEC  48
#define G3    1536   // 3*H
#define CIN   1024   // 2*H
#define FHOUT 96

// ---------------- scratch (__device__ globals; no allocation allowed) ----------------
__device__ float g_GI0[(size_t)TENC * NSEQ * G3];   // encoder gi, [t][n][j]   (~192 MB)
__device__ float g_GI1[(size_t)TDEC * NSEQ * G3];   // decoder gi (x1 part + bih), [t][n][j]
__device__ float g_WeT[(size_t)CIN * G3];           // W_ih_enc transposed: [c][j]
__device__ float g_WdT[(size_t)HID * G3];           // W_ih_dec right half transposed: [c][j]
__device__ float g_hA[NSEQ * HID];
__device__ float g_hB[NSEQ * HID];

// ---------------- weight transpose: dst[c][j] = src[j][cOff + c] ----------------
__global__ void transpose_w(const float* __restrict__ src, int which) {
    __shared__ float tile[32][33];
    float* dst = which ? g_WdT : g_WeT;
    int cOff   = which ? 512 : 0;
    int c0 = blockIdx.x * 32, j0 = blockIdx.y * 32;
    int x = threadIdx.x, y = threadIdx.y;
    #pragma unroll
    for (int yy = y; yy < 32; yy += 8)
        tile[yy][x] = src[(size_t)(j0 + yy) * CIN + cOff + c0 + x];
    __syncthreads();
    #pragma unroll
    for (int yy = y; yy < 32; yy += 8)
        dst[(size_t)(c0 + yy) * G3 + j0 + x] = tile[x][yy];
}

__global__ void zero_h() {
    int i = blockIdx.x * 256 + threadIdx.x;
    if (i < NSEQ * HID) g_hA[i] = 0.f;
}

// ---------------- encoder GI GEMM ----------------
// C[m, j] = sum_c X0[b, c, t0] * W_ih_enc[j, c] + bih[j],  m = b*512 + t0
// output scatter: t=t0>>1, n=((t0&1)<<6)|b  ->  g_GI0[t][n][j]
__global__ void __launch_bounds__(256) gemm_enc(const float* __restrict__ X0,
                                                const float* __restrict__ bih) {
    __shared__ float As[16][128];
    __shared__ float Bs[16][128];
    int m0 = blockIdx.y * 128, j0 = blockIdx.x * 128;
    int tid = threadIdx.x;
    int tx = tid & 15, ty = tid >> 4;
    int bb = m0 >> 9;          // whole tile lies in one b (512 % 128 == 0)
    int t0base = m0 & 511;
    float acc[8][8];
    #pragma unroll
    for (int u = 0; u < 8; u++)
        #pragma unroll
        for (int v = 0; v < 8; v++) acc[u][v] = 0.f;

    for (int c0 = 0; c0 < CIN; c0 += 16) {
        #pragma unroll
        for (int l = 0; l < 2; l++) {
            int idx4 = tid + 256 * l;
            int mm4 = idx4 & 31, cc = idx4 >> 5;
            float4 va = *(const float4*)(X0 + ((size_t)(bb * CIN + c0 + cc)) * 512 + t0base + mm4 * 4);
            *(float4*)(&As[cc][mm4 * 4]) = va;
            float4 vb = *(const float4*)(g_WeT + (size_t)(c0 + cc) * G3 + j0 + mm4 * 4);
            *(float4*)(&Bs[cc][mm4 * 4]) = vb;
        }
        __syncthreads();
        #pragma unroll
        for (int k = 0; k < 16; k++) {
            float a[8], bv[8];
            #pragma unroll
            for (int u = 0; u < 8; u++) a[u] = As[k][ty * 8 + u];
            #pragma unroll
            for (int v = 0; v < 8; v++) bv[v] = Bs[k][tx * 8 + v];
            #pragma unroll
            for (int u = 0; u < 8; u++)
                #pragma unroll
                for (int v = 0; v < 8; v++) acc[u][v] += a[u] * bv[v];
        }
        __syncthreads();
    }
    float bias[8];
    #pragma unroll
    for (int v = 0; v < 8; v++) bias[v] = bih[j0 + tx * 8 + v];
    #pragma unroll
    for (int u = 0; u < 8; u++) {
        int m = m0 + ty * 8 + u;
        int t0 = m & 511;
        int n = ((t0 & 1) << 6) | (m >> 9);
        size_t base = ((size_t)((t0 >> 1) * NSEQ + n)) * G3 + j0 + tx * 8;
        float4 o1, o2;
        o1.x = acc[u][0] + bias[0]; o1.y = acc[u][1] + bias[1];
        o1.z = acc[u][2] + bias[2]; o1.w = acc[u][3] + bias[3];
        o2.x = acc[u][4] + bias[4]; o2.y = acc[u][5] + bias[5];
        o2.z = acc[u][6] + bias[6]; o2.w = acc[u][7] + bias[7];
        *(float4*)(g_GI0 + base)     = o1;
        *(float4*)(g_GI0 + base + 4) = o2;
    }
}

// ---------------- decoder GI GEMM (x1 part) ----------------
// C[m, j] = sum_c X1[b, c, t0] * W_ih_dec[j, 512+c] + bih_dec[j],  m = b*96 + t0
__global__ void __launch_bounds__(256) gemm_dec(const float* __restrict__ X1,
                                                const float* __restrict__ bih) {
    __shared__ float As[16][128];
    __shared__ float Bs[16][128];
    int m0 = blockIdx.y * 128, j0 = blockIdx.x * 128;
    int tid = threadIdx.x;
    int tx = tid & 15, ty = tid >> 4;
    float acc[8][8];
    #pragma unroll
    for (int u = 0; u < 8; u++)
        #pragma unroll
        for (int v = 0; v < 8; v++) acc[u][v] = 0.f;

    for (int c0 = 0; c0 < HID; c0 += 16) {
        #pragma unroll
        for (int l = 0; l < 8; l++) {            // A: scalar loads (rows cross b boundaries)
            int idx = tid + 256 * l;
            int r = idx & 127, cc = idx >> 7;
            int m = m0 + r;
            int b = m / 96;
            int t0 = m - b * 96;
            As[cc][r] = X1[((size_t)(b * HID + c0 + cc)) * 96 + t0];
        }
        #pragma unroll
        for (int l = 0; l < 2; l++) {            // B: float4 coalesced
            int idx4 = tid + 256 * l;
            int jj4 = idx4 & 31, cc = idx4 >> 5;
            float4 vb = *(const float4*)(g_WdT + (size_t)(c0 + cc) * G3 + j0 + jj4 * 4);
            *(float4*)(&Bs[cc][jj4 * 4]) = vb;
        }
        __syncthreads();
        #pragma unroll
        for (int k = 0; k < 16; k++) {
            float a[8], bv[8];
            #pragma unroll
            for (int u = 0; u < 8; u++) a[u] = As[k][ty * 8 + u];
            #pragma unroll
            for (int v = 0; v < 8; v++) bv[v] = Bs[k][tx * 8 + v];
            #pragma unroll
            for (int u = 0; u < 8; u++)
                #pragma unroll
                for (int v = 0; v < 8; v++) acc[u][v] += a[u] * bv[v];
        }
        __syncthreads();
    }
    float bias[8];
    #pragma unroll
    for (int v = 0; v < 8; v++) bias[v] = bih[j0 + tx * 8 + v];
    #pragma unroll
    for (int u = 0; u < 8; u++) {
        int m = m0 + ty * 8 + u;
        int b = m / 96;
        int t0 = m - b * 96;
        int n = ((t0 & 1) << 6) | b;
        size_t base = ((size_t)((t0 >> 1) * NSEQ + n)) * G3 + j0 + tx * 8;
        float4 o1, o2;
        o1.x = acc[u][0] + bias[0]; o1.y = acc[u][1] + bias[1];
        o1.z = acc[u][2] + bias[2]; o1.w = acc[u][3] + bias[3];
        o2.x = acc[u][4] + bias[4]; o2.y = acc[u][5] + bias[5];
        o2.z = acc[u][6] + bias[6]; o2.w = acc[u][7] + bias[7];
        *(float4*)(g_GI1 + base)     = o1;
        *(float4*)(g_GI1 + base + 4) = o2;
    }
}

// ---------------- encoder step ----------------
// CTA jb owns hidden units [jb*4, jb*4+4). 12 W_hh rows resident in SMEM.
__global__ void __launch_bounds__(256) enc_step(const float* __restrict__ Whh,
                                                const float* __restrict__ bhh,
                                                const float* __restrict__ hin,
                                                float* __restrict__ hout, int t) {
    extern __shared__ float sm[];
    float* sw  = sm;                 // 12*512
    float* sgi = sw + 12 * 512;      // 12*128
    float* sb  = sgi + 12 * 128;     // 16
    float* sh  = sb + 16;            // 128*68
    int tid = threadIdx.x;
    int jb = blockIdx.x;             // 0..127

    #pragma unroll
    for (int l = 0; l < 24; l++) {
        int idx = tid + 256 * l;
        int q = idx >> 9, k = idx & 511;
        int j = jb * 4 + (q & 3) + (q >> 2) * 512;
        sw[idx] = Whh[(size_t)j * 512 + k];
    }
    if (tid < 12) sb[tid] = bhh[jb * 4 + (tid & 3) + (tid >> 2) * 512];
    #pragma unroll
    for (int l = 0; l < 6; l++) {
        int idx = tid + 256 * l;
        int n = idx & 127, q = idx >> 7;
        int j = jb * 4 + (q & 3) + (q >> 2) * 512;
        sgi[q * 128 + n] = g_GI0[((size_t)t * NSEQ + n) * G3 + j];
    }

    float acc[2][3] = {{0.f, 0.f, 0.f}, {0.f, 0.f, 0.f}};
    int n = tid & 127, half = tid >> 7;

    for (int k0 = 0; k0 < 512; k0 += 64) {
        __syncthreads();
        #pragma unroll
        for (int l = 0; l < 8; l++) {
            int idx4 = tid + 256 * l;
            int nn = idx4 >> 4, kq = idx4 & 15;
            *(float4*)(sh + nn * 68 + kq * 4) = *(const float4*)(hin + nn * 512 + k0 + kq * 4);
        }
        __syncthreads();
        #pragma unroll
        for (int kk = 0; kk < 16; kk++) {
            float4 h4 = *(const float4*)(sh + n * 68 + kk * 4);
            #pragma unroll
            for (int g = 0; g < 3; g++)
                #pragma unroll
                for (int p = 0; p < 2; p++) {
                    int q = g * 4 + half * 2 + p;
                    float4 w4 = *(const float4*)(sw + q * 512 + k0 + kk * 4);
                    acc[p][g] += h4.x * w4.x + h4.y * w4.y + h4.z * w4.z + h4.w * w4.w;
                }
        }
    }

    #pragma unroll
    for (int p = 0; p < 2; p++) {
        int jl = half * 2 + p;
        int jh = jb * 4 + jl;
        float r  = 1.f / (1.f + expf(-(sgi[(0 + jl) * 128 + n] + acc[p][0] + sb[jl])));
        float z  = 1.f / (1.f + expf(-(sgi[(4 + jl) * 128 + n] + acc[p][1] + sb[4 + jl])));
        float nn = tanhf(sgi[(8 + jl) * 128 + n] + r * (acc[p][2] + sb[8 + jl]));
        float hold = hin[n * 512 + jh];
        hout[n * 512 + jh] = (1.f - z) * nn + z * hold;
    }
}

// ---------------- decoder step ----------------
// din == previous h, so gi's din-part folds into the recurrent matmul.
// sw rows 0..11: W_hh_dec; rows 12..23: W_ih_dec[:, :512].
__global__ void __launch_bounds__(256) dec_step(const float* __restrict__ Whh,
                                                const float* __restrict__ Wih,
                                                const float* __restrict__ bhh,
                                                const float* __restrict__ hin,
                                                float* __restrict__ hout,
                                                float* __restrict__ out, int t) {
    extern __shared__ float sm[];
    float* sw  = sm;                 // 24*512
    float* sgi = sw + 24 * 512;      // 12*128
    float* sb  = sgi + 12 * 128;     // 16
    float* sh  = sb + 16;            // 128*68
    int tid = threadIdx.x;
    int jb = blockIdx.x;

    #pragma unroll
    for (int l = 0; l < 48; l++) {
        int idx = tid + 256 * l;
        int q2 = idx >> 9, k = idx & 511;
        if (q2 < 12) {
            int j = jb * 4 + (q2 & 3) + (q2 >> 2) * 512;
            sw[idx] = Whh[(size_t)j * 512 + k];
        } else {
            int q = q2 - 12;
            int j = jb * 4 + (q & 3) + (q >> 2) * 512;
            sw[idx] = Wih[(size_t)j * CIN + k];   // left half of W_ih_dec
        }
    }
    if (tid < 12) sb[tid] = bhh[jb * 4 + (tid & 3) + (tid >> 2) * 512];
    #pragma unroll
    for (int l = 0; l < 6; l++) {
        int idx = tid + 256 * l;
        int n = idx & 127, q = idx >> 7;
        int j = jb * 4 + (q & 3) + (q >> 2) * 512;
        sgi[q * 128 + n] = g_GI1[((size_t)t * NSEQ + n) * G3 + j];
    }

    float accH[2][3] = {{0.f, 0.f, 0.f}, {0.f, 0.f, 0.f}};
    float accI[2][3] = {{0.f, 0.f, 0.f}, {0.f, 0.f, 0.f}};
    int n = tid & 127, half = tid >> 7;

    for (int k0 = 0; k0 < 512; k0 += 64) {
        __syncthreads();
        #pragma unroll
        for (int l = 0; l < 8; l++) {
            int idx4 = tid + 256 * l;
            int nn = idx4 >> 4, kq = idx4 & 15;
            *(float4*)(sh + nn * 68 + kq * 4) = *(const float4*)(hin + nn * 512 + k0 + kq * 4);
        }
        __syncthreads();
        #pragma unroll
        for (int kk = 0; kk < 16; kk++) {
            float4 h4 = *(const float4*)(sh + n * 68 + kk * 4);
            #pragma unroll
            for (int g = 0; g < 3; g++)
                #pragma unroll
                for (int p = 0; p < 2; p++) {
                    int q = g * 4 + half * 2 + p;
                    float4 wh = *(const float4*)(sw + q * 512 + k0 + kk * 4);
                    accH[p][g] += h4.x * wh.x + h4.y * wh.y + h4.z * wh.z + h4.w * wh.w;
                    float4 wi = *(const float4*)(sw + (12 + q) * 512 + k0 + kk * 4);
                    accI[p][g] += h4.x * wi.x + h4.y * wi.y + h4.z * wi.z + h4.w * wi.w;
                }
        }
    }

    #pragma unroll
    for (int p = 0; p < 2; p++) {
        int jl = half * 2 + p;
        int jh = jb * 4 + jl;
        float r  = 1.f / (1.f + expf(-(sgi[(0 + jl) * 128 + n] + accI[p][0] + accH[p][0] + sb[jl])));
        float z  = 1.f / (1.f + expf(-(sgi[(4 + jl) * 128 + n] + accI[p][1] + accH[p][1] + sb[4 + jl])));
        float nn = tanhf((sgi[(8 + jl) * 128 + n] + accI[p][2]) + r * (accH[p][2] + sb[8 + jl]));
        float hold = hin[n * 512 + jh];
        float hnew = (1.f - z) * nn + z * hold;
        hout[n * 512 + jh] = hnew;
        int i_ = n >> 6, b = n & 63;
        int t0 = 2 * t + i_;                       // always < 96 for t <= 47
        out[(size_t)(b * HID + jh) * 96 + t0] = hnew;
    }
}

// ---------------- launch ----------------
extern "C" void kernel_launch(void* const* d_in, const int* in_sizes, int n_in,
                              void* d_out, int out_size) {
    const float* X0  = (const float*)d_in[0];
    const float* X1  = (const float*)d_in[1];
    const float* Wie = (const float*)d_in[3];
    const float* Whe = (const float*)d_in[4];
    const float* bie = (const float*)d_in[5];
    const float* bhe = (const float*)d_in[6];
    const float* Wid = (const float*)d_in[7];
    const float* Whd = (const float*)d_in[8];
    const float* bid = (const float*)d_in[9];
    const float* bhd = (const float*)d_in[10];
    float* out = (float*)d_out;

    const int SMEM_ENC = (12 * 512 + 12 * 128 + 16 + 128 * 68) * 4;  // 65600 B
    const int SMEM_DEC = (24 * 512 + 12 * 128 + 16 + 128 * 68) * 4;  // 90176 B
    cudaFuncSetAttribute(enc_step, cudaFuncAttributeMaxDynamicSharedMemorySize, SMEM_ENC);
    cudaFuncSetAttribute(dec_step, cudaFuncAttributeMaxDynamicSharedMemorySize, SMEM_DEC);

    float *hA, *hB;
    cudaGetSymbolAddress((void**)&hA, g_hA);
    cudaGetSymbolAddress((void**)&hB, g_hB);

    dim3 tb(32, 8);
    transpose_w<<<dim3(CIN / 32, G3 / 32), tb>>>(Wie, 0);
    transpose_w<<<dim3(HID / 32, G3 / 32), tb>>>(Wid, 1);
    zero_h<<<256, 256>>>();
    gemm_enc<<<dim3(G3 / 128, (BATCH * 512) / 128), 256>>>(X0, bie);
    gemm_dec<<<dim3(G3 / 128, (BATCH * 96) / 128), 256>>>(X1, bid);

    int cur = 0;
    for (int t = 0; t < TENC; t++) {
        enc_step<<<128, 256, SMEM_ENC>>>(Whe, bhe, cur ? hB : hA, cur ? hA : hB, t);
        cur ^= 1;
    }
    for (int t = 0; t < TDEC; t++) {
        dec_step<<<128, 256, SMEM_DEC>>>(Whd, Wid, bhd, cur ? hB : hA, cur ? hA : hB, out, t);
        cur ^= 1;
    }
}

// round 2
// speedup vs baseline: 1.8950x; 1.8950x over previous
#include <cuda_runtime.h>
#include <math.h>

#define HID   512
#define BATCH 64
#define NSEQ  128
#define TENC  256
#define TDEC  48
#define G3    1536   // 3*H
#define CIN   1024   // 2*H

#define SW_STRIDE 520   // weight row stride (floats): 520%32=8 -> b*8 banks, conflict-free
#define SH_STRIDE 68    // h row stride (floats): 68%32=4 -> a*4 banks, conflict-free

// ---------------- scratch ----------------
__device__ float g_GI0[(size_t)TENC * NSEQ * G3];
__device__ float g_GI1[(size_t)TDEC * NSEQ * G3];
__device__ float g_WeT[(size_t)CIN * G3];
__device__ float g_WdT[(size_t)HID * G3];
__device__ float g_hA[NSEQ * HID];
__device__ float g_hB[NSEQ * HID];
__device__ unsigned g_bar_count = 0;
__device__ unsigned g_bar_gen   = 0;

// ---------------- f32x2 helpers ----------------
__device__ __forceinline__ void fma2(unsigned long long& acc, double a, double b) {
    asm("fma.rn.f32x2 %0, %1, %2, %0;"
        : "+l"(acc)
        : "l"(__double_as_longlong(a)), "l"(__double_as_longlong(b)));
}
__device__ __forceinline__ float pairsum(unsigned long long v) {
    return __uint_as_float((unsigned)v) + __uint_as_float((unsigned)(v >> 32));
}
__device__ __forceinline__ float sigmoidf_(float x) { return 1.f / (1.f + expf(-x)); }

// ---------------- grid barrier (all 128 CTAs resident: single wave) ----------------
__device__ __forceinline__ void grid_barrier() {
    __syncthreads();
    if (threadIdx.x == 0) {
        unsigned g0 = atomicAdd(&g_bar_gen, 0u);
        __threadfence();
        if (atomicAdd(&g_bar_count, 1u) == gridDim.x - 1) {
            g_bar_count = 0;
            __threadfence();
            atomicAdd(&g_bar_gen, 1u);
        } else {
            while (atomicAdd(&g_bar_gen, 0u) == g0) { }
        }
        __threadfence();
    }
    __syncthreads();
}

// ---------------- weight transpose ----------------
__global__ void transpose_w(const float* __restrict__ src, int which) {
    __shared__ float tile[32][33];
    float* dst = which ? g_WdT : g_WeT;
    int cOff   = which ? 512 : 0;
    int c0 = blockIdx.x * 32, j0 = blockIdx.y * 32;
    int x = threadIdx.x, y = threadIdx.y;
    #pragma unroll
    for (int yy = y; yy < 32; yy += 8)
        tile[yy][x] = src[(size_t)(j0 + yy) * CIN + cOff + c0 + x];
    __syncthreads();
    #pragma unroll
    for (int yy = y; yy < 32; yy += 8)
        dst[(size_t)(c0 + yy) * G3 + j0 + x] = tile[x][yy];
}

__global__ void zero_h() {
    int i = blockIdx.x * 256 + threadIdx.x;
    if (i < NSEQ * HID) g_hA[i] = 0.f;
}

// ---------------- encoder GI GEMM (unchanged, near fp32 roofline) ----------------
__global__ void __launch_bounds__(256) gemm_enc(const float* __restrict__ X0,
                                                const float* __restrict__ bih) {
    __shared__ float As[16][128];
    __shared__ float Bs[16][128];
    int m0 = blockIdx.y * 128, j0 = blockIdx.x * 128;
    int tid = threadIdx.x;
    int tx = tid & 15, ty = tid >> 4;
    int bb = m0 >> 9;
    int t0base = m0 & 511;
    float acc[8][8];
    #pragma unroll
    for (int u = 0; u < 8; u++)
        #pragma unroll
        for (int v = 0; v < 8; v++) acc[u][v] = 0.f;

    for (int c0 = 0; c0 < CIN; c0 += 16) {
        #pragma unroll
        for (int l = 0; l < 2; l++) {
            int idx4 = tid + 256 * l;
            int mm4 = idx4 & 31, cc = idx4 >> 5;
            float4 va = *(const float4*)(X0 + ((size_t)(bb * CIN + c0 + cc)) * 512 + t0base + mm4 * 4);
            *(float4*)(&As[cc][mm4 * 4]) = va;
            float4 vb = *(const float4*)(g_WeT + (size_t)(c0 + cc) * G3 + j0 + mm4 * 4);
            *(float4*)(&Bs[cc][mm4 * 4]) = vb;
        }
        __syncthreads();
        #pragma unroll
        for (int k = 0; k < 16; k++) {
            float a[8], bv[8];
            #pragma unroll
            for (int u = 0; u < 8; u++) a[u] = As[k][ty * 8 + u];
            #pragma unroll
            for (int v = 0; v < 8; v++) bv[v] = Bs[k][tx * 8 + v];
            #pragma unroll
            for (int u = 0; u < 8; u++)
                #pragma unroll
                for (int v = 0; v < 8; v++) acc[u][v] += a[u] * bv[v];
        }
        __syncthreads();
    }
    float bias[8];
    #pragma unroll
    for (int v = 0; v < 8; v++) bias[v] = bih[j0 + tx * 8 + v];
    #pragma unroll
    for (int u = 0; u < 8; u++) {
        int m = m0 + ty * 8 + u;
        int t0 = m & 511;
        int n = ((t0 & 1) << 6) | (m >> 9);
        size_t base = ((size_t)((t0 >> 1) * NSEQ + n)) * G3 + j0 + tx * 8;
        float4 o1, o2;
        o1.x = acc[u][0] + bias[0]; o1.y = acc[u][1] + bias[1];
        o1.z = acc[u][2] + bias[2]; o1.w = acc[u][3] + bias[3];
        o2.x = acc[u][4] + bias[4]; o2.y = acc[u][5] + bias[5];
        o2.z = acc[u][6] + bias[6]; o2.w = acc[u][7] + bias[7];
        *(float4*)(g_GI0 + base)     = o1;
        *(float4*)(g_GI0 + base + 4) = o2;
    }
}

// ---------------- decoder GI GEMM (unchanged) ----------------
__global__ void __launch_bounds__(256) gemm_dec(const float* __restrict__ X1,
                                                const float* __restrict__ bih) {
    __shared__ float As[16][128];
    __shared__ float Bs[16][128];
    int m0 = blockIdx.y * 128, j0 = blockIdx.x * 128;
    int tid = threadIdx.x;
    int tx = tid & 15, ty = tid >> 4;
    float acc[8][8];
    #pragma unroll
    for (int u = 0; u < 8; u++)
        #pragma unroll
        for (int v = 0; v < 8; v++) acc[u][v] = 0.f;

    for (int c0 = 0; c0 < HID; c0 += 16) {
        #pragma unroll
        for (int l = 0; l < 8; l++) {
            int idx = tid + 256 * l;
            int r = idx & 127, cc = idx >> 7;
            int m = m0 + r;
            int b = m / 96;
            int t0 = m - b * 96;
            As[cc][r] = X1[((size_t)(b * HID + c0 + cc)) * 96 + t0];
        }
        #pragma unroll
        for (int l = 0; l < 2; l++) {
            int idx4 = tid + 256 * l;
            int jj4 = idx4 & 31, cc = idx4 >> 5;
            float4 vb = *(const float4*)(g_WdT + (size_t)(c0 + cc) * G3 + j0 + jj4 * 4);
            *(float4*)(&Bs[cc][jj4 * 4]) = vb;
        }
        __syncthreads();
        #pragma unroll
        for (int k = 0; k < 16; k++) {
            float a[8], bv[8];
            #pragma unroll
            for (int u = 0; u < 8; u++) a[u] = As[k][ty * 8 + u];
            #pragma unroll
            for (int v = 0; v < 8; v++) bv[v] = Bs[k][tx * 8 + v];
            #pragma unroll
            for (int u = 0; u < 8; u++)
                #pragma unroll
                for (int v = 0; v < 8; v++) acc[u][v] += a[u] * bv[v];
        }
        __syncthreads();
    }
    float bias[8];
    #pragma unroll
    for (int v = 0; v < 8; v++) bias[v] = bih[j0 + tx * 8 + v];
    #pragma unroll
    for (int u = 0; u < 8; u++) {
        int m = m0 + ty * 8 + u;
        int b = m / 96;
        int t0 = m - b * 96;
        int n = ((t0 & 1) << 6) | b;
        size_t base = ((size_t)((t0 >> 1) * NSEQ + n)) * G3 + j0 + tx * 8;
        float4 o1, o2;
        o1.x = acc[u][0] + bias[0]; o1.y = acc[u][1] + bias[1];
        o1.z = acc[u][2] + bias[2]; o1.w = acc[u][3] + bias[3];
        o2.x = acc[u][4] + bias[4]; o2.y = acc[u][5] + bias[5];
        o2.z = acc[u][6] + bias[6]; o2.w = acc[u][7] + bias[7];
        *(float4*)(g_GI1 + base)     = o1;
        *(float4*)(g_GI1 + base + 4) = o2;
    }
}

// ---------------- persistent recurrence kernel ----------------
// 128 CTAs (one per SM, single wave). CTA jb owns hidden units jb*4..jb*4+3.
// Thread (a = tid>>2, b = tid&3): n in {a, a+64}, j-local = b, gates g=0..2.
// Weights in SMEM (rows q=g*4+b, stride 520). h staged per 64-k chunk, double-buffered.
__global__ void __launch_bounds__(256, 1) rnn_persist(
    const float* __restrict__ Whe, const float* __restrict__ bhe,
    const float* __restrict__ Whd, const float* __restrict__ Wid,
    const float* __restrict__ bhd, float* __restrict__ out)
{
    extern __shared__ float sm[];
    float* sw  = sm;                                  // 24 * 520
    float* sh0 = sm + 24 * SW_STRIDE;                 // 128 * 68
    float* sh1 = sh0 + 128 * SH_STRIDE;               // 128 * 68

    int tid = threadIdx.x;
    int jb  = blockIdx.x;
    int a   = tid >> 2;
    int b   = tid & 3;
    int n0  = a, n1 = a + 64;
    int jh  = jb * 4 + b;

    // staging index constants
    int s_nn = tid >> 4;         // + 16*l
    int s_kq = tid & 15;

    // ---- encoder weights: rows g*4+b' -> Whe[jb*4 + b' + 512g] ----
    #pragma unroll
    for (int l = 0; l < 24; l++) {
        int idx = tid + 256 * l;              // 0..6143
        int q = idx >> 9, k = idx & 511;
        int j = jb * 4 + (q & 3) + (q >> 2) * 512;
        sw[q * SW_STRIDE + k] = Whe[(size_t)j * 512 + k];
    }
    float bias[3];
    #pragma unroll
    for (int g = 0; g < 3; g++) bias[g] = bhe[jh + 512 * g];
    __syncthreads();

    const float* wp0 = sw + b * SW_STRIDE;
    const float* wp1 = sw + (4 + b) * SW_STRIDE;
    const float* wp2 = sw + (8 + b) * SW_STRIDE;

    const float* hin  = g_hA;
    float*       hout = g_hB;

    // =================== ENCODER: 256 steps ===================
    for (int t = 0; t < TENC; t++) {
        // GI for this step -> registers (exactly the 6 scalars this thread needs)
        const float* gp = g_GI0 + (size_t)t * NSEQ * G3;
        float gi0r = gp[(size_t)n0 * G3 + jh];
        float gi0z = gp[(size_t)n0 * G3 + jh + 512];
        float gi0n = gp[(size_t)n0 * G3 + jh + 1024];
        float gi1r = gp[(size_t)n1 * G3 + jh];
        float gi1z = gp[(size_t)n1 * G3 + jh + 512];
        float gi1n = gp[(size_t)n1 * G3 + jh + 1024];

        unsigned long long acc[2][3] = {{0ull,0ull,0ull},{0ull,0ull,0ull}};

        // prologue: stage chunk 0
        float4 preg[8];
        #pragma unroll
        for (int l = 0; l < 8; l++)
            preg[l] = *(const float4*)(hin + (s_nn + 16 * l) * 512 + s_kq * 4);
        #pragma unroll
        for (int l = 0; l < 8; l++)
            *(float4*)(sh0 + (s_nn + 16 * l) * SH_STRIDE + s_kq * 4) = preg[l];
        __syncthreads();

        #pragma unroll
        for (int c = 0; c < 8; c++) {
            const float* shc = (c & 1) ? sh1 : sh0;
            float*       shn = (c & 1) ? sh0 : sh1;
            int k0 = c * 64;
            if (c < 7) {
                #pragma unroll
                for (int l = 0; l < 8; l++)
                    preg[l] = *(const float4*)(hin + (s_nn + 16 * l) * 512 + (k0 + 64) + s_kq * 4);
            }
            #pragma unroll
            for (int kk = 0; kk < 16; kk++) {
                double2 h0 = *(const double2*)(shc + n0 * SH_STRIDE + kk * 4);
                double2 h1 = *(const double2*)(shc + n1 * SH_STRIDE + kk * 4);
                double2 w0 = *(const double2*)(wp0 + k0 + kk * 4);
                double2 w1 = *(const double2*)(wp1 + k0 + kk * 4);
                double2 w2 = *(const double2*)(wp2 + k0 + kk * 4);
                fma2(acc[0][0], h0.x, w0.x); fma2(acc[0][0], h0.y, w0.y);
                fma2(acc[1][0], h1.x, w0.x); fma2(acc[1][0], h1.y, w0.y);
                fma2(acc[0][1], h0.x, w1.x); fma2(acc[0][1], h0.y, w1.y);
                fma2(acc[1][1], h1.x, w1.x); fma2(acc[1][1], h1.y, w1.y);
                fma2(acc[0][2], h0.x, w2.x); fma2(acc[0][2], h0.y, w2.y);
                fma2(acc[1][2], h1.x, w2.x); fma2(acc[1][2], h1.y, w2.y);
            }
            if (c < 7) {
                #pragma unroll
                for (int l = 0; l < 8; l++)
                    *(float4*)(shn + (s_nn + 16 * l) * SH_STRIDE + s_kq * 4) = preg[l];
            }
            __syncthreads();
        }

        // epilogue: gates
        {
            float ar = pairsum(acc[0][0]) + bias[0];
            float az = pairsum(acc[0][1]) + bias[1];
            float an = pairsum(acc[0][2]) + bias[2];
            float r = sigmoidf_(gi0r + ar);
            float z = sigmoidf_(gi0z + az);
            float nn = tanhf(gi0n + r * an);
            float hold = hin[n0 * 512 + jh];
            hout[n0 * 512 + jh] = (1.f - z) * nn + z * hold;
        }
        {
            float ar = pairsum(acc[1][0]) + bias[0];
            float az = pairsum(acc[1][1]) + bias[1];
            float an = pairsum(acc[1][2]) + bias[2];
            float r = sigmoidf_(gi1r + ar);
            float z = sigmoidf_(gi1z + az);
            float nn = tanhf(gi1n + r * an);
            float hold = hin[n1 * 512 + jh];
            hout[n1 * 512 + jh] = (1.f - z) * nn + z * hold;
        }

        grid_barrier();
        const float* tmp = hin; hin = hout; hout = (float*)tmp;
    }

    // ---- decoder weights: rows 0..11 = Whd, rows 12..23 = Wih_dec left half ----
    #pragma unroll
    for (int l = 0; l < 48; l++) {
        int idx = tid + 256 * l;              // 0..12287
        int q2 = idx >> 9, k = idx & 511;
        if (q2 < 12) {
            int j = jb * 4 + (q2 & 3) + (q2 >> 2) * 512;
            sw[q2 * SW_STRIDE + k] = Whd[(size_t)j * 512 + k];
        } else {
            int q = q2 - 12;
            int j = jb * 4 + (q & 3) + (q >> 2) * 512;
            sw[q2 * SW_STRIDE + k] = Wid[(size_t)j * CIN + k];
        }
    }
    #pragma unroll
    for (int g = 0; g < 3; g++) bias[g] = bhd[jh + 512 * g];
    __syncthreads();

    const float* ip0 = sw + (12 + b) * SW_STRIDE;
    const float* ip1 = sw + (16 + b) * SW_STRIDE;
    const float* ip2 = sw + (20 + b) * SW_STRIDE;

    // =================== DECODER: 48 steps ===================
    for (int t = 0; t < TDEC; t++) {
        const float* gp = g_GI1 + (size_t)t * NSEQ * G3;
        float gi0r = gp[(size_t)n0 * G3 + jh];
        float gi0z = gp[(size_t)n0 * G3 + jh + 512];
        float gi0n = gp[(size_t)n0 * G3 + jh + 1024];
        float gi1r = gp[(size_t)n1 * G3 + jh];
        float gi1z = gp[(size_t)n1 * G3 + jh + 512];
        float gi1n = gp[(size_t)n1 * G3 + jh + 1024];

        unsigned long long accH[2][3] = {{0ull,0ull,0ull},{0ull,0ull,0ull}};
        unsigned long long accI[2][3] = {{0ull,0ull,0ull},{0ull,0ull,0ull}};

        float4 preg[8];
        #pragma unroll
        for (int l = 0; l < 8; l++)
            preg[l] = *(const float4*)(hin + (s_nn + 16 * l) * 512 + s_kq * 4);
        #pragma unroll
        for (int l = 0; l < 8; l++)
            *(float4*)(sh0 + (s_nn + 16 * l) * SH_STRIDE + s_kq * 4) = preg[l];
        __syncthreads();

        #pragma unroll
        for (int c = 0; c < 8; c++) {
            const float* shc = (c & 1) ? sh1 : sh0;
            float*       shn = (c & 1) ? sh0 : sh1;
            int k0 = c * 64;
            if (c < 7) {
                #pragma unroll
                for (int l = 0; l < 8; l++)
                    preg[l] = *(const float4*)(hin + (s_nn + 16 * l) * 512 + (k0 + 64) + s_kq * 4);
            }
            #pragma unroll
            for (int kk = 0; kk < 16; kk++) {
                double2 h0 = *(const double2*)(shc + n0 * SH_STRIDE + kk * 4);
                double2 h1 = *(const double2*)(shc + n1 * SH_STRIDE + kk * 4);
                double2 w0 = *(const double2*)(wp0 + k0 + kk * 4);
                double2 w1 = *(const double2*)(wp1 + k0 + kk * 4);
                double2 w2 = *(const double2*)(wp2 + k0 + kk * 4);
                fma2(accH[0][0], h0.x, w0.x); fma2(accH[0][0], h0.y, w0.y);
                fma2(accH[1][0], h1.x, w0.x); fma2(accH[1][0], h1.y, w0.y);
                fma2(accH[0][1], h0.x, w1.x); fma2(accH[0][1], h0.y, w1.y);
                fma2(accH[1][1], h1.x, w1.x); fma2(accH[1][1], h1.y, w1.y);
                fma2(accH[0][2], h0.x, w2.x); fma2(accH[0][2], h0.y, w2.y);
                fma2(accH[1][2], h1.x, w2.x); fma2(accH[1][2], h1.y, w2.y);
                double2 v0 = *(const double2*)(ip0 + k0 + kk * 4);
                double2 v1 = *(const double2*)(ip1 + k0 + kk * 4);
                double2 v2 = *(const double2*)(ip2 + k0 + kk * 4);
                fma2(accI[0][0], h0.x, v0.x); fma2(accI[0][0], h0.y, v0.y);
                fma2(accI[1][0], h1.x, v0.x); fma2(accI[1][0], h1.y, v0.y);
                fma2(accI[0][1], h0.x, v1.x); fma2(accI[0][1], h0.y, v1.y);
                fma2(accI[1][1], h1.x, v1.x); fma2(accI[1][1], h1.y, v1.y);
                fma2(accI[0][2], h0.x, v2.x); fma2(accI[0][2], h0.y, v2.y);
                fma2(accI[1][2], h1.x, v2.x); fma2(accI[1][2], h1.y, v2.y);
            }
            if (c < 7) {
                #pragma unroll
                for (int l = 0; l < 8; l++)
                    *(float4*)(shn + (s_nn + 16 * l) * SH_STRIDE + s_kq * 4) = preg[l];
            }
            __syncthreads();
        }

        // epilogue (n0: i_=0, batch=a; n1: i_=1, batch=a)
        {
            float hr = pairsum(accH[0][0]) + bias[0];
            float hz = pairsum(accH[0][1]) + bias[1];
            float hn = pairsum(accH[0][2]) + bias[2];
            float r = sigmoidf_(gi0r + pairsum(accI[0][0]) + hr);
            float z = sigmoidf_(gi0z + pairsum(accI[0][1]) + hz);
            float nn = tanhf(gi0n + pairsum(accI[0][2]) + r * hn);
            float hold = hin[n0 * 512 + jh];
            float hnew = (1.f - z) * nn + z * hold;
            hout[n0 * 512 + jh] = hnew;
            out[((size_t)a * HID + jh) * 96 + 2 * t] = hnew;
        }
        {
            float hr = pairsum(accH[1][0]) + bias[0];
            float hz = pairsum(accH[1][1]) + bias[1];
            float hn = pairsum(accH[1][2]) + bias[2];
            float r = sigmoidf_(gi1r + pairsum(accI[1][0]) + hr);
            float z = sigmoidf_(gi1z + pairsum(accI[1][1]) + hz);
            float nn = tanhf(gi1n + pairsum(accI[1][2]) + r * hn);
            float hold = hin[n1 * 512 + jh];
            float hnew = (1.f - z) * nn + z * hold;
            hout[n1 * 512 + jh] = hnew;
            out[((size_t)a * HID + jh) * 96 + 2 * t + 1] = hnew;
        }

        if (t < TDEC - 1) {
            grid_barrier();
            const float* tmp = hin; hin = hout; hout = (float*)tmp;
        }
    }
}

// ---------------- launch ----------------
extern "C" void kernel_launch(void* const* d_in, const int* in_sizes, int n_in,
                              void* d_out, int out_size) {
    const float* X0  = (const float*)d_in[0];
    const float* X1  = (const float*)d_in[1];
    const float* Wie = (const float*)d_in[3];
    const float* Whe = (const float*)d_in[4];
    const float* bie = (const float*)d_in[5];
    const float* bhe = (const float*)d_in[6];
    const float* Wid = (const float*)d_in[7];
    const float* Whd = (const float*)d_in[8];
    const float* bid = (const float*)d_in[9];
    const float* bhd = (const float*)d_in[10];
    float* out = (float*)d_out;

    const int SMEM_P = (24 * SW_STRIDE + 2 * 128 * SH_STRIDE) * 4;  // 119552 B
    cudaFuncSetAttribute(rnn_persist, cudaFuncAttributeMaxDynamicSharedMemorySize, SMEM_P);

    dim3 tb(32, 8);
    transpose_w<<<dim3(CIN / 32, G3 / 32), tb>>>(Wie, 0);
    transpose_w<<<dim3(HID / 32, G3 / 32), tb>>>(Wid, 1);
    zero_h<<<256, 256>>>();
    gemm_enc<<<dim3(G3 / 128, (BATCH * 512) / 128), 256>>>(X0, bie);
    gemm_dec<<<dim3(G3 / 128, (BATCH * 96) / 128), 256>>>(X1, bid);

    rnn_persist<<<128, 256, SMEM_P>>>(Whe, bhe, Whd, Wid, bhd, out);
}